// round 16
// baseline (speedup 1.0000x reference)
#include <cuda_runtime.h>
#include <mma.h>
#include <cstdint>

using namespace nvcuda;

#define FDIM 128
#define BPAD 132          // padded smem row stride (floats): kills bank conflicts
#define MAXN 200704
#define MAXE 602112
#define MAXB 256          // max scan blocks (256*1024 >= MAXN)
#define SBLK 512          // col_stats partial blocks
#define PF   8            // prefetched edges per node (deg>PF tail is ~1%)

// Scratch (device globals; no allocation allowed)
__device__ float g_buf0[MAXN * FDIM];   // xw (GEMM output, pre-aggregation)
__device__ float g_buf1[MAXN * FDIM];   // layer-1 aggregated h1 (layer-2 GEMM input)
__device__ int   g_degi[MAXN];
__device__ float g_dinv[MAXN];
__device__ int   g_rowp[MAXN + 1];
__device__ int   g_cursor[MAXN];
__device__ int   g_bsum[MAXB];
__device__ int   g_boff[MAXB];
__device__ float2 g_edge[MAXE];         // packed (src-as-float-bits, coef)
__device__ float g_part_s[SBLK * FDIM]; // col_stats partial sums
__device__ float g_part_q[SBLK * FDIM]; // col_stats partial sumsq
__device__ float g_W1p[FDIM * FDIM];    // W1 / sigma  (standardization folded)
__device__ float g_c1[FDIM];            // -(mu/sigma) @ W1
__device__ int   g_ei64;                // edge_index is int64?
__device__ int   g_b64;                 // batch is int64?

// ---------------------------------------------------------------------------
__device__ __forceinline__ int load_idx(const void* p, long long e, int is64) {
    return is64 ? (int)((const long long*)p)[e] : ((const int*)p)[e];
}

// Detect int64 vs int32 by inspecting raw 32-bit words (values < 2^31 ->
// int64 little-endian has all odd words zero). Parallel probe.
__global__ void detect_dtype(const int* ei_w, int E, const int* b_w, int N) {
    __shared__ int nz;
    if (threadIdx.x == 0) nz = 0;
    __syncthreads();
    if (blockIdx.x == 0) {
        int lim = 2 * E < 2048 ? 2 * E : 2048;
        for (int i = 1 + 2 * threadIdx.x; i < lim; i += 2 * blockDim.x)
            if (ei_w[i] != 0) atomicAdd(&nz, 1);
        __syncthreads();
        if (threadIdx.x == 0) g_ei64 = (nz == 0) ? 1 : 0;
    } else {
        int start = N - 2048; if (start < 0) start = 0;
        for (int i = start + threadIdx.x; i < N; i += blockDim.x)
            if ((i & 1) && b_w[i] != 0) atomicAdd(&nz, 1);
        __syncthreads();
        if (threadIdx.x == 0) g_b64 = (nz == 0) ? 1 : 0;
    }
}

// Column partial sums / sums of squares of x; atomic-free (per-block slots).
__global__ void col_stats(const float* __restrict__ x, int N) {
    int col = threadIdx.x;  // blockDim = 128
    float s = 0.f, s2 = 0.f;
    for (int r = blockIdx.x; r < N; r += SBLK) {
        float v = x[(size_t)r * FDIM + col];
        s += v; s2 += v * v;
    }
    g_part_s[blockIdx.x * FDIM + col] = s;
    g_part_q[blockIdx.x * FDIM + col] = s2;
}

// Fold standardization into W1:  x_std @ W1 = x @ (W1/sigma) + c
__global__ void prep_kernel(const float* __restrict__ W1, int N) {
    __shared__ float mu[FDIM], isd[FDIM];
    int t = threadIdx.x;  // 128 threads
    float sum = 0.f, sq = 0.f;
    for (int b = 0; b < SBLK; b++) {
        sum += g_part_s[b * FDIM + t];
        sq  += g_part_q[b * FDIM + t];
    }
    float mean = sum / (float)N;
    float var = (sq - sum * mean) / (float)(N - 1);  // ddof=1
    mu[t] = mean;
    isd[t] = rsqrtf(var);
    __syncthreads();
    float c = 0.f;
    for (int f = 0; f < FDIM; f++) {
        float w = W1[f * FDIM + t];
        g_W1p[f * FDIM + t] = w * isd[f];
        c -= mu[f] * isd[f] * w;
    }
    g_c1[t] = c;
}

__global__ void zero_kernel(float* __restrict__ dout, int outN, int N) {
    int i = blockIdx.x * blockDim.x + threadIdx.x;
    if (i < N)    { g_degi[i] = 0; g_cursor[i] = 0; }
    if (i < outN) dout[i] = 0.f;
}

__global__ void deg_count(const void* __restrict__ ei, int E) {
    int e = blockIdx.x * blockDim.x + threadIdx.x;
    if (e < E) {
        int d = load_idx(ei, (long long)E + e, g_ei64);
        atomicAdd(&g_degi[d], 1);
    }
}

// ---------------------------------------------------------------------------
// CSR build: exclusive prefix sum of g_degi -> g_rowp, then bin edges.
__global__ void scan1(int N) {
    __shared__ int sh[256];
    int t = threadIdx.x;
    int base = blockIdx.x * 1024 + t * 4;
    int v[4]; int s = 0;
#pragma unroll
    for (int i = 0; i < 4; i++) {
        v[i] = (base + i < N) ? g_degi[base + i] : 0;
        s += v[i];
    }
    sh[t] = s; __syncthreads();
    for (int off = 1; off < 256; off <<= 1) {
        int x = (t >= off) ? sh[t - off] : 0;
        __syncthreads();
        sh[t] += x;
        __syncthreads();
    }
    int run = sh[t] - s;   // exclusive
    if (t == 255) g_bsum[blockIdx.x] = sh[255];
#pragma unroll
    for (int i = 0; i < 4; i++) {
        if (base + i < N) { g_rowp[base + i] = run; run += v[i]; }
    }
}

__global__ void scan2(int NB) {
    __shared__ int sh[256];
    int t = threadIdx.x;
    int v = (t < NB) ? g_bsum[t] : 0;
    sh[t] = v; __syncthreads();
    for (int off = 1; off < 256; off <<= 1) {
        int x = (t >= off) ? sh[t - off] : 0;
        __syncthreads();
        sh[t] += x;
        __syncthreads();
    }
    if (t < NB) g_boff[t] = sh[t] - v;
}

// scan3 + dinv fused (both elementwise over N).
__global__ void scan3(int N, int E) {
    int i = blockIdx.x * blockDim.x + threadIdx.x;
    if (i < N) {
        g_rowp[i] += g_boff[i >> 10];
        g_dinv[i] = rsqrtf((float)g_degi[i] + 1.0f);
    }
    if (i == 0) g_rowp[N] = E;
}

__global__ void bin_edges(const void* __restrict__ ei, int E) {
    int e = blockIdx.x * blockDim.x + threadIdx.x;
    if (e >= E) return;
    int is64 = g_ei64;
    int s = load_idx(ei, e, is64);
    int d = load_idx(ei, (long long)E + e, is64);
    int pos = g_rowp[d] + atomicAdd(&g_cursor[d], 1);
    g_edge[pos] = make_float2(__int_as_float(s), g_dinv[s] * g_dinv[d]);
}

// ---------------------------------------------------------------------------
// GEMM: C[M,128] = A[M,128] @ B[128,128]  (tf32 wmma, B in padded smem).
// Round-13 design: 8 warps, warp tile 32x64, block tile 128x128, A fragments
// straight from global (L2 catches the 2x reuse), direct fp32 fragment
// stores. 2 blocks/SM. RELU_A: relu applied to A on load (layer 2).
template <bool RELU_A>
__global__ void __launch_bounds__(256, 2)
gemm_kernel(const float* __restrict__ A, const float* __restrict__ B,
            float* __restrict__ Cxw, int M)
{
    extern __shared__ float sB[];  // 128*BPAD floats = 66 KB
    for (int i = threadIdx.x; i < FDIM * FDIM; i += 256) {
        int r = i >> 7, c = i & 127;
        sB[r * BPAD + c] = wmma::__float_to_tf32(B[i]);
    }
    __syncthreads();

    int warp = threadIdx.x >> 5;
    int mrow = warp & 3;        // 0..3  -> M offset
    int ncol = warp >> 2;       // 0..1  -> N offset
    int row0 = blockIdx.x * 128 + mrow * 32;
    int col0 = ncol * 64;
    if (row0 + 32 > M) return;

    wmma::fragment<wmma::accumulator, 16, 16, 8, float> acc[2][4];
#pragma unroll
    for (int i = 0; i < 2; i++)
#pragma unroll
        for (int j = 0; j < 4; j++) wmma::fill_fragment(acc[i][j], 0.f);

#pragma unroll
    for (int k = 0; k < FDIM; k += 8) {
        wmma::fragment<wmma::matrix_a, 16, 16, 8, wmma::precision::tf32, wmma::row_major> a[2];
#pragma unroll
        for (int i = 0; i < 2; i++) {
            wmma::load_matrix_sync(a[i], A + (size_t)(row0 + i * 16) * FDIM + k, FDIM);
#pragma unroll
            for (int t = 0; t < a[i].num_elements; t++) {
                float v = a[i].x[t];
                if (RELU_A) v = fmaxf(v, 0.f);
                a[i].x[t] = wmma::__float_to_tf32(v);
            }
        }
        wmma::fragment<wmma::matrix_b, 16, 16, 8, wmma::precision::tf32, wmma::row_major> b[4];
#pragma unroll
        for (int j = 0; j < 4; j++)
            wmma::load_matrix_sync(b[j], sB + k * BPAD + col0 + j * 16, BPAD);
#pragma unroll
        for (int i = 0; i < 2; i++)
#pragma unroll
            for (int j = 0; j < 4; j++)
                wmma::mma_sync(acc[i][j], a[i], b[j], acc[i][j]);
    }

#pragma unroll
    for (int i = 0; i < 2; i++)
#pragma unroll
        for (int j = 0; j < 4; j++)
            wmma::store_matrix_sync(Cxw + (size_t)(row0 + i * 16) * FDIM + col0 + j * 16,
                                    acc[i][j], FDIM, wmma::mem_row_major);
}

// ---------------------------------------------------------------------------
__device__ __forceinline__ void red_add_v4(float* p, float4 v) {
    asm volatile("red.global.add.v4.f32 [%0], {%1, %2, %3, %4};"
                 :: "l"(p), "f"(v.x), "f"(v.y), "f"(v.z), "f"(v.w) : "memory");
}

// Atomic-free segmented aggregation: one warp owns one dst node's full row.
// LATENCY-OPTIMIZED: edge records (up to PF) and the self row are loaded
// FIRST as independent requests, then all gathers issue with known addresses
// — breaks the serial edge->gather dependency chain.
//   h[d] = sum_e coef_e*xw[src_e] + dinv_d^2*xw[d] (+ fac*c1) + bias
// POOL=false: write h to out[d] (layer 1).
// POOL=true:  out[batch[d]] += relu(h)  (layer 2 fused with global_add_pool).
template <bool POOL, bool ADD_C>
__global__ void aggregate(const float* __restrict__ xw, float* __restrict__ out,
                          const float* __restrict__ bias, const float* __restrict__ cvec,
                          const void* __restrict__ batch, int N)
{
    int node = (int)((blockIdx.x * (unsigned)blockDim.x + threadIdx.x) >> 5);
    int lane = threadIdx.x & 31;
    if (node >= N) return;
    int beg = g_rowp[node];
    int end = g_rowp[node + 1];
    int deg = end - beg;
    int pf = deg < PF ? deg : PF;

    // Phase 1: independent loads — edge records (8B broadcast) + self row.
    float2 ed[PF];
#pragma unroll
    for (int i = 0; i < PF; i++)
        if (i < pf) ed[i] = g_edge[beg + i];
    float4 self = __ldg((const float4*)(xw + (size_t)node * FDIM) + lane);

    // Phase 2: gathers (addresses now known; issue back-to-back).
    float4 acc = make_float4(0.f, 0.f, 0.f, 0.f);
    float csum = 0.f;
#pragma unroll
    for (int i = 0; i < PF; i++) {
        if (i < pf) {
            int s = __float_as_int(ed[i].x);
            float c = ed[i].y;
            csum += c;
            float4 v = __ldg((const float4*)(xw + (size_t)s * FDIM) + lane);
            acc.x += c * v.x; acc.y += c * v.y; acc.z += c * v.z; acc.w += c * v.w;
        }
    }
    // Tail for deg > PF (rare).
    for (int e = beg + PF; e < end; e++) {
        float2 edt = g_edge[e];
        int s = __float_as_int(edt.x);
        float c = edt.y;
        csum += c;
        float4 v = __ldg((const float4*)(xw + (size_t)s * FDIM) + lane);
        acc.x += c * v.x; acc.y += c * v.y; acc.z += c * v.z; acc.w += c * v.w;
    }

    float di = g_dinv[node];
    float sc = di * di;
    float fac = csum + sc;
    float4 b = ((const float4*)bias)[lane];
    acc.x += sc * self.x + b.x;
    acc.y += sc * self.y + b.y;
    acc.z += sc * self.z + b.z;
    acc.w += sc * self.w + b.w;
    if (ADD_C) {
        float4 cv = ((const float4*)cvec)[lane];
        acc.x += fac * cv.x; acc.y += fac * cv.y;
        acc.z += fac * cv.z; acc.w += fac * cv.w;
    }
    if (POOL) {
        acc.x = fmaxf(acc.x, 0.f); acc.y = fmaxf(acc.y, 0.f);
        acc.z = fmaxf(acc.z, 0.f); acc.w = fmaxf(acc.w, 0.f);
        int g = load_idx(batch, node, g_b64);
        red_add_v4(out + (size_t)g * FDIM + lane * 4, acc);
    } else {
        ((float4*)(out + (size_t)node * FDIM))[lane] = acc;
    }
}

// ---------------------------------------------------------------------------
extern "C" void kernel_launch(void* const* d_in, const int* in_sizes, int n_in,
                              void* d_out, int out_size)
{
    const float* x     = (const float*)d_in[0];
    const void*  ei    = d_in[1];          // [2,E], int32 or int64 (device-detected)
    const void*  batch = d_in[2];

    int N = in_sizes[0] / FDIM;
    int E = in_sizes[1] / 2;

    const float* wb[4] = {nullptr, nullptr, nullptr, nullptr};
    const int want[4] = {FDIM * FDIM, FDIM, FDIM * FDIM, FDIM};
    int slot = 0;
    for (int i = 3; i < n_in && slot < 4; i++) {
        if (in_sizes[i] <= 2) continue;
        if (in_sizes[i] == want[slot]) wb[slot++] = (const float*)d_in[i];
    }
    if (slot < 4 && n_in >= 7) {
        for (int k = 0; k < 4; k++) wb[k] = (const float*)d_in[n_in - 4 + k];
    }
    const float* W1 = wb[0];
    const float* b1 = wb[1];
    const float* W2 = wb[2];
    const float* b2 = wb[3];

    float* out = (float*)d_out;

    float *p0, *p1, *pW1p, *pc1;
    cudaGetSymbolAddress((void**)&p0,   g_buf0);
    cudaGetSymbolAddress((void**)&p1,   g_buf1);
    cudaGetSymbolAddress((void**)&pW1p, g_W1p);
    cudaGetSymbolAddress((void**)&pc1,  g_c1);

    const int SMEM = FDIM * BPAD * sizeof(float);  // 66 KB (padded)
    cudaFuncSetAttribute(gemm_kernel<false>,
                         cudaFuncAttributeMaxDynamicSharedMemorySize, SMEM);
    cudaFuncSetAttribute(gemm_kernel<true>,
                         cudaFuncAttributeMaxDynamicSharedMemorySize, SMEM);

    int gblocks = (N + 127) / 128;
    int ablocks = (N + 7) / 8;   // 8 warps (nodes) per 256-thread block
    int NB = (N + 1023) / 1024;

    // Launch order chosen so gemm1 sits in the ncu capture slot (4th launch).
    detect_dtype<<<2, 1024>>>((const int*)ei, E, (const int*)batch, N);       // 0
    col_stats<<<SBLK, 128>>>(x, N);                                           // 1
    prep_kernel<<<1, 128>>>(W1, N);                                           // 2
    gemm_kernel<false><<<gblocks, 256, SMEM>>>(x, pW1p, p0, N);               // 3 <- profiled
    zero_kernel<<<(N + 255) / 256, 256>>>(out, out_size, N);                  // 4
    deg_count<<<(E + 255) / 256, 256>>>(ei, E);                               // 5
    scan1<<<NB, 256>>>(N);                                                    // 6
    scan2<<<1, 256>>>(NB);                                                    // 7
    scan3<<<(N + 255) / 256, 256>>>(N, E);                                    // 8
    bin_edges<<<(E + 255) / 256, 256>>>(ei, E);                               // 9
    aggregate<false, true><<<ablocks, 256>>>(p0, p1, b1, pc1, batch, N);      // 10
    gemm_kernel<true><<<gblocks, 256, SMEM>>>(p1, W2, p0, N);                 // 11
    aggregate<true, false><<<ablocks, 256>>>(p0, out, b2, nullptr, batch, N); // 12
}

// round 17
// speedup vs baseline: 1.3674x; 1.3674x over previous
#include <cuda_runtime.h>
#include <cuda_bf16.h>
#include <mma.h>
#include <cstdint>

using namespace nvcuda;

#define FDIM 128
#define BPAD 132          // padded smem row stride for B (floats)
#define SPAD 24           // per-warp fragment stage stride (floats, 16B-aligned rows)
#define MAXN 200704
#define MAXE 602112
#define MAXB 256          // max scan blocks (256*1024 >= MAXN)
#define SBLK 512          // col_stats partial blocks

// Scratch (device globals; no allocation allowed)
__device__ __nv_bfloat16 g_xw[MAXN * FDIM];  // GEMM output bf16 (gather operand)
__device__ float g_buf1[MAXN * FDIM];        // layer-1 aggregated h1 (fp32, GEMM2 input)
__device__ int   g_degi[MAXN];
__device__ float g_dinv[MAXN];
__device__ int   g_rowp[MAXN + 1];
__device__ int   g_cursor[MAXN];
__device__ int   g_bsum[MAXB];
__device__ int   g_boff[MAXB];
__device__ float2 g_edge[MAXE];              // packed (src-as-float-bits, coef)
__device__ float g_part_s[SBLK * FDIM];      // col_stats partial sums
__device__ float g_part_q[SBLK * FDIM];      // col_stats partial sumsq
__device__ float g_W1p[FDIM * FDIM];         // W1 / sigma  (standardization folded)
__device__ float g_c1[FDIM];                 // -(mu/sigma) @ W1
__device__ int   g_ei64;                     // edge_index is int64?
__device__ int   g_b64;                      // batch is int64?

// ---------------------------------------------------------------------------
__device__ __forceinline__ int load_idx(const void* p, long long e, int is64) {
    return is64 ? (int)((const long long*)p)[e] : ((const int*)p)[e];
}

// Detect int64 vs int32 by inspecting raw 32-bit words (values < 2^31 ->
// int64 little-endian has all odd words zero). Parallel probe.
__global__ void detect_dtype(const int* ei_w, int E, const int* b_w, int N) {
    __shared__ int nz;
    if (threadIdx.x == 0) nz = 0;
    __syncthreads();
    if (blockIdx.x == 0) {
        int lim = 2 * E < 2048 ? 2 * E : 2048;
        for (int i = 1 + 2 * threadIdx.x; i < lim; i += 2 * blockDim.x)
            if (ei_w[i] != 0) atomicAdd(&nz, 1);
        __syncthreads();
        if (threadIdx.x == 0) g_ei64 = (nz == 0) ? 1 : 0;
    } else {
        int start = N - 2048; if (start < 0) start = 0;
        for (int i = start + threadIdx.x; i < N; i += blockDim.x)
            if ((i & 1) && b_w[i] != 0) atomicAdd(&nz, 1);
        __syncthreads();
        if (threadIdx.x == 0) g_b64 = (nz == 0) ? 1 : 0;
    }
}

// Column partial sums / sums of squares of x; atomic-free (per-block slots).
__global__ void col_stats(const float* __restrict__ x, int N) {
    int col = threadIdx.x;  // blockDim = 128
    float s = 0.f, s2 = 0.f;
    for (int r = blockIdx.x; r < N; r += SBLK) {
        float v = x[(size_t)r * FDIM + col];
        s += v; s2 += v * v;
    }
    g_part_s[blockIdx.x * FDIM + col] = s;
    g_part_q[blockIdx.x * FDIM + col] = s2;
}

// Fold standardization into W1:  x_std @ W1 = x @ (W1/sigma) + c
__global__ void prep_kernel(const float* __restrict__ W1, int N) {
    __shared__ float mu[FDIM], isd[FDIM];
    int t = threadIdx.x;  // 128 threads
    float sum = 0.f, sq = 0.f;
    for (int b = 0; b < SBLK; b++) {
        sum += g_part_s[b * FDIM + t];
        sq  += g_part_q[b * FDIM + t];
    }
    float mean = sum / (float)N;
    float var = (sq - sum * mean) / (float)(N - 1);  // ddof=1
    mu[t] = mean;
    isd[t] = rsqrtf(var);
    __syncthreads();
    float c = 0.f;
    for (int f = 0; f < FDIM; f++) {
        float w = W1[f * FDIM + t];
        g_W1p[f * FDIM + t] = w * isd[f];
        c -= mu[f] * isd[f] * w;
    }
    g_c1[t] = c;
}

__global__ void zero_kernel(float* __restrict__ dout, int outN, int N) {
    int i = blockIdx.x * blockDim.x + threadIdx.x;
    if (i < N)    { g_degi[i] = 0; g_cursor[i] = 0; }
    if (i < outN) dout[i] = 0.f;
}

__global__ void deg_count(const void* __restrict__ ei, int E) {
    int e = blockIdx.x * blockDim.x + threadIdx.x;
    if (e < E) {
        int d = load_idx(ei, (long long)E + e, g_ei64);
        atomicAdd(&g_degi[d], 1);
    }
}

// ---------------------------------------------------------------------------
// CSR build: exclusive prefix sum of g_degi -> g_rowp, then bin edges.
__global__ void scan1(int N) {
    __shared__ int sh[256];
    int t = threadIdx.x;
    int base = blockIdx.x * 1024 + t * 4;
    int v[4]; int s = 0;
#pragma unroll
    for (int i = 0; i < 4; i++) {
        v[i] = (base + i < N) ? g_degi[base + i] : 0;
        s += v[i];
    }
    sh[t] = s; __syncthreads();
    for (int off = 1; off < 256; off <<= 1) {
        int x = (t >= off) ? sh[t - off] : 0;
        __syncthreads();
        sh[t] += x;
        __syncthreads();
    }
    int run = sh[t] - s;   // exclusive
    if (t == 255) g_bsum[blockIdx.x] = sh[255];
#pragma unroll
    for (int i = 0; i < 4; i++) {
        if (base + i < N) { g_rowp[base + i] = run; run += v[i]; }
    }
}

__global__ void scan2(int NB) {
    __shared__ int sh[256];
    int t = threadIdx.x;
    int v = (t < NB) ? g_bsum[t] : 0;
    sh[t] = v; __syncthreads();
    for (int off = 1; off < 256; off <<= 1) {
        int x = (t >= off) ? sh[t - off] : 0;
        __syncthreads();
        sh[t] += x;
        __syncthreads();
    }
    if (t < NB) g_boff[t] = sh[t] - v;
}

// scan3 + dinv fused (both elementwise over N).
__global__ void scan3(int N, int E) {
    int i = blockIdx.x * blockDim.x + threadIdx.x;
    if (i < N) {
        g_rowp[i] += g_boff[i >> 10];
        g_dinv[i] = rsqrtf((float)g_degi[i] + 1.0f);
    }
    if (i == 0) g_rowp[N] = E;
}

__global__ void bin_edges(const void* __restrict__ ei, int E) {
    int e = blockIdx.x * blockDim.x + threadIdx.x;
    if (e >= E) return;
    int is64 = g_ei64;
    int s = load_idx(ei, e, is64);
    int d = load_idx(ei, (long long)E + e, is64);
    int pos = g_rowp[d] + atomicAdd(&g_cursor[d], 1);
    g_edge[pos] = make_float2(__int_as_float(s), g_dinv[s] * g_dinv[d]);
}

// ---------------------------------------------------------------------------
// GEMM: C[M,128] = A[M,128] @ B[128,128]  (tf32 wmma, B in padded smem).
// Round-13 mainloop (8 warps, warp tile 32x64, A fragments from global — L2
// catches the 2x reuse). bf16 epilogue with NO block syncs: each warp stages
// one 16x16 fragment at a time into its PRIVATE smem slab (ldm=SPAD), packs
// bf16x2, writes 16B per lane. RELU_A: relu applied to A on load (layer 2).
template <bool RELU_A>
__global__ void __launch_bounds__(256, 2)
gemm_kernel(const float* __restrict__ A, const float* __restrict__ B,
            __nv_bfloat16* __restrict__ Cxw, int M)
{
    extern __shared__ float sm[];
    float* sB = sm;                                   // 128*BPAD floats
    for (int i = threadIdx.x; i < FDIM * FDIM; i += 256) {
        int r = i >> 7, c = i & 127;
        sB[r * BPAD + c] = wmma::__float_to_tf32(B[i]);
    }
    __syncthreads();

    int warp = threadIdx.x >> 5;
    int lane = threadIdx.x & 31;
    int mrow = warp & 3;        // 0..3  -> M offset
    int ncol = warp >> 2;       // 0..1  -> N offset
    int row0 = blockIdx.x * 128 + mrow * 32;
    int col0 = ncol * 64;
    if (row0 + 32 > M) return;  // no block syncs below

    wmma::fragment<wmma::accumulator, 16, 16, 8, float> acc[2][4];
#pragma unroll
    for (int i = 0; i < 2; i++)
#pragma unroll
        for (int j = 0; j < 4; j++) wmma::fill_fragment(acc[i][j], 0.f);

#pragma unroll
    for (int k = 0; k < FDIM; k += 8) {
        wmma::fragment<wmma::matrix_a, 16, 16, 8, wmma::precision::tf32, wmma::row_major> a[2];
#pragma unroll
        for (int i = 0; i < 2; i++) {
            wmma::load_matrix_sync(a[i], A + (size_t)(row0 + i * 16) * FDIM + k, FDIM);
#pragma unroll
            for (int t = 0; t < a[i].num_elements; t++) {
                float v = a[i].x[t];
                if (RELU_A) v = fmaxf(v, 0.f);
                a[i].x[t] = wmma::__float_to_tf32(v);
            }
        }
        wmma::fragment<wmma::matrix_b, 16, 16, 8, wmma::precision::tf32, wmma::row_major> b[4];
#pragma unroll
        for (int j = 0; j < 4; j++)
            wmma::load_matrix_sync(b[j], sB + k * BPAD + col0 + j * 16, BPAD);
#pragma unroll
        for (int i = 0; i < 2; i++)
#pragma unroll
            for (int j = 0; j < 4; j++)
                wmma::mma_sync(acc[i][j], a[i], b[j], acc[i][j]);
    }

    // bf16 epilogue: per-warp private stage (16 rows x SPAD floats), syncwarp only.
    float* stage = sm + FDIM * BPAD + warp * 16 * SPAD;
    int r = lane >> 1;          // 0..15 fragment row
    int half = lane & 1;        // 8-col half
#pragma unroll
    for (int i = 0; i < 2; i++) {
#pragma unroll
        for (int j = 0; j < 4; j++) {
            wmma::store_matrix_sync(stage, acc[i][j], SPAD, wmma::mem_row_major);
            __syncwarp();
            const float* src = stage + r * SPAD + half * 8;
            float4 a0 = *(const float4*)(src);
            float4 a1 = *(const float4*)(src + 4);
            uint4 o;
            __nv_bfloat162 p;
            p = __float22bfloat162_rn(make_float2(a0.x, a0.y)); o.x = *(uint32_t*)&p;
            p = __float22bfloat162_rn(make_float2(a0.z, a0.w)); o.y = *(uint32_t*)&p;
            p = __float22bfloat162_rn(make_float2(a1.x, a1.y)); o.z = *(uint32_t*)&p;
            p = __float22bfloat162_rn(make_float2(a1.z, a1.w)); o.w = *(uint32_t*)&p;
            *(uint4*)(Cxw + (size_t)(row0 + i * 16 + r) * FDIM + col0 + j * 16 + half * 8) = o;
            __syncwarp();   // stage reused next fragment
        }
    }
}

// ---------------------------------------------------------------------------
__device__ __forceinline__ void red_add_v4(float* p, float4 v) {
    asm volatile("red.global.add.v4.f32 [%0], {%1, %2, %3, %4};"
                 :: "l"(p), "f"(v.x), "f"(v.y), "f"(v.z), "f"(v.w) : "memory");
}

__device__ __forceinline__ float4 bf16row_ld(const __nv_bfloat16* row, int lane) {
    uint2 u = __ldg((const uint2*)row + lane);
    __nv_bfloat162 p0 = *reinterpret_cast<__nv_bfloat162*>(&u.x);
    __nv_bfloat162 p1 = *reinterpret_cast<__nv_bfloat162*>(&u.y);
    float2 f0 = __bfloat1622float2(p0);
    float2 f1 = __bfloat1622float2(p1);
    return make_float4(f0.x, f0.y, f1.x, f1.y);
}

// Atomic-free segmented aggregation over bf16 xw: one warp per dst node.
// SERIAL edge loop on purpose — front-batched gathers regress on B300
// (cross-CTA L1tex-queue contention).
//   h[d] = sum_e coef_e*xw[src_e] + dinv_d^2*xw[d] (+ fac*c1) + bias
// POOL=false: write h (fp32) to out[d] (layer 1).
// POOL=true:  out[batch[d]] += relu(h)  (layer 2 fused with global_add_pool).
template <bool POOL, bool ADD_C>
__global__ void aggregate(const __nv_bfloat16* __restrict__ xw, float* __restrict__ out,
                          const float* __restrict__ bias, const float* __restrict__ cvec,
                          const void* __restrict__ batch, int N)
{
    int node = (int)((blockIdx.x * (unsigned)blockDim.x + threadIdx.x) >> 5);
    int lane = threadIdx.x & 31;
    if (node >= N) return;
    int beg = g_rowp[node];
    int end = g_rowp[node + 1];
    float4 acc = make_float4(0.f, 0.f, 0.f, 0.f);
    float csum = 0.f;
    for (int e = beg; e < end; e++) {
        float2 ed = g_edge[e];
        int s = __float_as_int(ed.x);
        float c = ed.y;
        csum += c;
        float4 v = bf16row_ld(xw + (size_t)s * FDIM, lane);
        acc.x += c * v.x; acc.y += c * v.y; acc.z += c * v.z; acc.w += c * v.w;
    }
    float di = g_dinv[node];
    float sc = di * di;
    float fac = csum + sc;
    float4 v = bf16row_ld(xw + (size_t)node * FDIM, lane);
    float4 b = ((const float4*)bias)[lane];
    acc.x += sc * v.x + b.x;
    acc.y += sc * v.y + b.y;
    acc.z += sc * v.z + b.z;
    acc.w += sc * v.w + b.w;
    if (ADD_C) {
        float4 cv = ((const float4*)cvec)[lane];
        acc.x += fac * cv.x; acc.y += fac * cv.y;
        acc.z += fac * cv.z; acc.w += fac * cv.w;
    }
    if (POOL) {
        acc.x = fmaxf(acc.x, 0.f); acc.y = fmaxf(acc.y, 0.f);
        acc.z = fmaxf(acc.z, 0.f); acc.w = fmaxf(acc.w, 0.f);
        int g = load_idx(batch, node, g_b64);
        red_add_v4(out + (size_t)g * FDIM + lane * 4, acc);
    } else {
        ((float4*)(out + (size_t)node * FDIM))[lane] = acc;
    }
}

// ---------------------------------------------------------------------------
extern "C" void kernel_launch(void* const* d_in, const int* in_sizes, int n_in,
                              void* d_out, int out_size)
{
    const float* x     = (const float*)d_in[0];
    const void*  ei    = d_in[1];          // [2,E], int32 or int64 (device-detected)
    const void*  batch = d_in[2];

    int N = in_sizes[0] / FDIM;
    int E = in_sizes[1] / 2;

    const float* wb[4] = {nullptr, nullptr, nullptr, nullptr};
    const int want[4] = {FDIM * FDIM, FDIM, FDIM * FDIM, FDIM};
    int slot = 0;
    for (int i = 3; i < n_in && slot < 4; i++) {
        if (in_sizes[i] <= 2) continue;
        if (in_sizes[i] == want[slot]) wb[slot++] = (const float*)d_in[i];
    }
    if (slot < 4 && n_in >= 7) {
        for (int k = 0; k < 4; k++) wb[k] = (const float*)d_in[n_in - 4 + k];
    }
    const float* W1 = wb[0];
    const float* b1 = wb[1];
    const float* W2 = wb[2];
    const float* b2 = wb[3];

    float* out = (float*)d_out;

    __nv_bfloat16* pxw;
    float *p1, *pW1p, *pc1;
    cudaGetSymbolAddress((void**)&pxw,  g_xw);
    cudaGetSymbolAddress((void**)&p1,   g_buf1);
    cudaGetSymbolAddress((void**)&pW1p, g_W1p);
    cudaGetSymbolAddress((void**)&pc1,  g_c1);

    // smem: B tile + 8 per-warp fragment stages
    const int SMEM = (FDIM * BPAD + 8 * 16 * SPAD) * sizeof(float);  // ~79.9 KB
    cudaFuncSetAttribute(gemm_kernel<false>,
                         cudaFuncAttributeMaxDynamicSharedMemorySize, SMEM);
    cudaFuncSetAttribute(gemm_kernel<true>,
                         cudaFuncAttributeMaxDynamicSharedMemorySize, SMEM);

    int gblocks = (N + 127) / 128;
    int ablocks = (N + 7) / 8;   // 8 warps (nodes) per 256-thread block
    int NB = (N + 1023) / 1024;

    // Launch order chosen so gemm1 sits in the ncu capture slot (4th launch).
    detect_dtype<<<2, 1024>>>((const int*)ei, E, (const int*)batch, N);       // 0
    col_stats<<<SBLK, 128>>>(x, N);                                           // 1
    prep_kernel<<<1, 128>>>(W1, N);                                           // 2
    gemm_kernel<false><<<gblocks, 256, SMEM>>>(x, pW1p, pxw, N);              // 3 <- profiled
    zero_kernel<<<(N + 255) / 256, 256>>>(out, out_size, N);                  // 4
    deg_count<<<(E + 255) / 256, 256>>>(ei, E);                               // 5
    scan1<<<NB, 256>>>(N);                                                    // 6
    scan2<<<1, 256>>>(NB);                                                    // 7
    scan3<<<(N + 255) / 256, 256>>>(N, E);                                    // 8
    bin_edges<<<(E + 255) / 256, 256>>>(ei, E);                               // 9
    aggregate<false, true><<<ablocks, 256>>>(pxw, p1, b1, pc1, batch, N);     // 10
    gemm_kernel<true><<<gblocks, 256, SMEM>>>(p1, W2, pxw, N);                // 11
    aggregate<true, false><<<ablocks, 256>>>(pxw, out, b2, nullptr, batch, N);// 12
}